// round 7
// baseline (speedup 1.0000x reference)
#include <cuda_runtime.h>
#include <cuda_bf16.h>
#include <cstdint>

#define NUM_CLASSES 1000
#define FEAT_DIM    256
#define N_ROWS      262144
#define ALPHA       0.5f
#define HB          64                     // histogram blocks
#define ROWS_PER_HB (N_ROWS / HB)          // 4096

// Scratch (device globals — no allocation allowed). No zero pass needed:
// every word below is fully overwritten each replay.
__device__ int g_parthist[HB * NUM_CLASSES];
__device__ int g_blockbase[HB * NUM_CLASSES];
__device__ int g_offsets[NUM_CLASSES];
__device__ int g_counts[NUM_CLASSES];
__device__ int g_rank[N_ROWS];
__device__ int g_rowidx[N_ROWS];

// ---------------------------------------------------------------------------
// K1: per-block smem histogram + within-(block,class) rank. No global atomics.
// ---------------------------------------------------------------------------
__global__ void __launch_bounds__(256)
hist_rank_kernel(const int* __restrict__ labels) {
    __shared__ int sh[NUM_CLASSES];
    int b = blockIdx.x;
    for (int c = threadIdx.x; c < NUM_CLASSES; c += 256) sh[c] = 0;
    __syncthreads();

    int base = b * ROWS_PER_HB;
    for (int j = threadIdx.x; j < ROWS_PER_HB; j += 256) {
        int i = base + j;
        int cls = labels[i];
        g_rank[i] = atomicAdd(&sh[cls], 1);   // smem atomic: ~2 cyc/lane
    }
    __syncthreads();
    for (int c = threadIdx.x; c < NUM_CLASSES; c += 256)
        g_parthist[b * NUM_CLASSES + c] = sh[c];
}

// ---------------------------------------------------------------------------
// K2: totals per class, exclusive class scan, per-(block,class) bases.
// Single block, 1024 threads; all data L2-hot (256 KB partials).
// ---------------------------------------------------------------------------
__global__ void scan_kernel() {
    __shared__ int sc[1024];
    int c = threadIdx.x;

    int total = 0;
    if (c < NUM_CLASSES) {
#pragma unroll 8
        for (int b = 0; b < HB; b++) total += g_parthist[b * NUM_CLASSES + c];
    }
    sc[c] = (c < NUM_CLASSES) ? total : 0;
    __syncthreads();
#pragma unroll
    for (int off = 1; off < 1024; off <<= 1) {
        int t = (c >= off) ? sc[c - off] : 0;
        __syncthreads();
        sc[c] += t;
        __syncthreads();
    }
    if (c < NUM_CLASSES) {
        int excl = sc[c] - total;
        g_offsets[c] = excl;
        g_counts[c] = total;
        int run = excl;
#pragma unroll 8
        for (int b = 0; b < HB; b++) {
            g_blockbase[b * NUM_CLASSES + c] = run;
            run += g_parthist[b * NUM_CLASSES + c];
        }
    }
}

// ---------------------------------------------------------------------------
// K3: place — atomic-free scatter. int4 loads, 4 rows/thread for MLP.
// ---------------------------------------------------------------------------
__global__ void __launch_bounds__(256)
place_kernel(const int* __restrict__ labels) {
    int t = blockIdx.x * blockDim.x + threadIdx.x;   // N_ROWS/4 threads
    int i = t * 4;
    int b = i >> 12;                                  // ROWS_PER_HB = 4096
    const int* __restrict__ bb = g_blockbase + b * NUM_CLASSES;

    int4 l = reinterpret_cast<const int4*>(labels)[t];
    int4 r = reinterpret_cast<const int4*>(g_rank)[t];

    g_rowidx[bb[l.x] + r.x] = i;
    g_rowidx[bb[l.y] + r.y] = i + 1;
    g_rowidx[bb[l.z] + r.z] = i + 2;
    g_rowidx[bb[l.w] + r.w] = i + 3;
}

// ---------------------------------------------------------------------------
// K4: gather-sum + fused mean/EMA. 500 blocks x 2 classes = single wave at
// 4 blocks/SM. 256 threads: tid -> (row slot r4 0..3, float4 column c4 0..63).
// Streaming (.cs) feature loads keep L2 for index arrays.
// ---------------------------------------------------------------------------
#define F4ADD(a, b) { (a).x += (b).x; (a).y += (b).y; (a).z += (b).z; (a).w += (b).w; }

__global__ void __launch_bounds__(256, 4)
sum_ema_kernel(const float* __restrict__ features,
               const float* __restrict__ centers,
               float* __restrict__ out) {
    int tid = threadIdx.x;
    int r4 = tid >> 6;   // row slot 0..3
    int c4 = tid & 63;   // float4 column 0..63

    __shared__ float4 s[256];
    const float4* __restrict__ f4 = reinterpret_cast<const float4*>(features);

#pragma unroll 1
    for (int sub = 0; sub < 2; sub++) {
        int cls = blockIdx.x * 2 + sub;
        int n = g_counts[cls];
        const int* __restrict__ ridx = g_rowidx + g_offsets[cls];

        float4 a0 = make_float4(0.f, 0.f, 0.f, 0.f);
        float4 a1 = a0, a2 = a0, a3 = a0;

        int i = r4;
        // 4-deep unroll x 4 row slots = 16 rows in flight per block iter.
        for (; i + 12 < n; i += 16) {
            int i0 = ridx[i];
            int i1 = ridx[i + 4];
            int i2 = ridx[i + 8];
            int i3 = ridx[i + 12];
            float4 v0 = __ldcs(&f4[(size_t)i0 * 64 + c4]);
            float4 v1 = __ldcs(&f4[(size_t)i1 * 64 + c4]);
            float4 v2 = __ldcs(&f4[(size_t)i2 * 64 + c4]);
            float4 v3 = __ldcs(&f4[(size_t)i3 * 64 + c4]);
            F4ADD(a0, v0); F4ADD(a1, v1); F4ADD(a2, v2); F4ADD(a3, v3);
        }
        for (; i < n; i += 4) {
            int r = ridx[i];
            float4 v = __ldcs(&f4[(size_t)r * 64 + c4]);
            F4ADD(a0, v);
        }
        F4ADD(a0, a1); F4ADD(a2, a3); F4ADD(a0, a2);

        s[tid] = a0;
        __syncthreads();

        if (tid < 64) {
            float4 t0 = s[tid];
            float4 t1 = s[tid + 64];
            float4 t2 = s[tid + 128];
            float4 t3 = s[tid + 192];
            F4ADD(t0, t1); F4ADD(t2, t3); F4ADD(t0, t2);

            float4 c = reinterpret_cast<const float4*>(centers)[(size_t)cls * 64 + tid];
            float4 o;
            if (n > 0) {
                float scale = ALPHA / (float)n;   // ALPHA * mean
                o.x = (1.0f - ALPHA) * c.x + scale * t0.x;
                o.y = (1.0f - ALPHA) * c.y + scale * t0.y;
                o.z = (1.0f - ALPHA) * c.z + scale * t0.z;
                o.w = (1.0f - ALPHA) * c.w + scale * t0.w;
            } else {
                o = c;
            }
            reinterpret_cast<float4*>(out)[(size_t)cls * 64 + tid] = o;
        }
        __syncthreads();   // smem reuse safety for second class
    }
}

// ---------------------------------------------------------------------------
// Launch: features f32 [N,256], labels i32 [N], centers f32 [1000,256].
// ---------------------------------------------------------------------------
extern "C" void kernel_launch(void* const* d_in, const int* in_sizes, int n_in,
                              void* d_out, int out_size) {
    const float* features = (const float*)d_in[0];
    const int* labels     = (const int*)d_in[1];
    const float* centers  = (const float*)d_in[2];
    float* out            = (float*)d_out;

    hist_rank_kernel<<<HB, 256>>>(labels);
    scan_kernel<<<1, 1024>>>();
    place_kernel<<<(N_ROWS / 4) / 256, 256>>>(labels);
    sum_ema_kernel<<<NUM_CLASSES / 2, 256>>>(features, centers, out);
}

// round 8
// speedup vs baseline: 1.0881x; 1.0881x over previous
#include <cuda_runtime.h>
#include <cuda_bf16.h>
#include <cstdint>

#define NUM_CLASSES 1000
#define CPAD        1024                   // padded class count
#define FEAT_DIM    256
#define N_ROWS      262144
#define ALPHA       0.5f
#define HB          64                     // index blocks (all co-resident)
#define ROWS_PER_HB (N_ROWS / HB)          // 4096
#define RPT         (ROWS_PER_HB / 256)    // 16 rows per thread

// Scratch (device globals — no allocation allowed).
__device__ int g_parthist[HB * CPAD];
__device__ int g_offsets[NUM_CLASSES];
__device__ int g_counts[NUM_CLASSES];
__device__ int g_rowidx[N_ROWS];
__device__ unsigned g_bar_cnt = 0;
__device__ unsigned g_bar_gen = 0;

// Grid-wide barrier: single use per launch; counter self-resets, generation
// bump releases waiters. All HB blocks are co-resident (64 << 148 SMs).
__device__ __forceinline__ void grid_barrier() {
    __syncthreads();
    if (threadIdx.x == 0) {
        __threadfence();
        unsigned gen = atomicAdd(&g_bar_gen, 0u);
        unsigned old = atomicAdd(&g_bar_cnt, 1u);
        if (old == HB - 1) {
            atomicExch(&g_bar_cnt, 0u);
            __threadfence();
            atomicAdd(&g_bar_gen, 1u);
        } else {
            while (atomicAdd(&g_bar_gen, 0u) == gen) { }
        }
        __threadfence();
    }
    __syncthreads();
}

// ---------------------------------------------------------------------------
// K1: fused index build — smem hist+rank (regs), barrier, redundant scan,
// direct place. No global atomics outside the barrier.
// ---------------------------------------------------------------------------
__global__ void __launch_bounds__(256)
index_kernel(const int* __restrict__ labels) {
    __shared__ int shA[CPAD];   // phase A: histogram; phase B: totals -> bases
    __shared__ int shP[CPAD];   // phase B: this block's prefix over earlier blocks
    __shared__ int shS[256];    // phase B: block scan of thread sums

    int tid = threadIdx.x;
    int myB = blockIdx.x;

    // --- Phase A: histogram + ranks (held in registers) ---
#pragma unroll
    for (int c = tid; c < CPAD; c += 256) shA[c] = 0;
    __syncthreads();

    const int4* __restrict__ lab4 = reinterpret_cast<const int4*>(labels);
    int base4 = myB * (ROWS_PER_HB / 4);

    int lab[RPT], rnk[RPT];
#pragma unroll
    for (int k = 0; k < RPT / 4; k++) {
        int4 L = lab4[base4 + tid + k * 256];
        lab[k * 4 + 0] = L.x; lab[k * 4 + 1] = L.y;
        lab[k * 4 + 2] = L.z; lab[k * 4 + 3] = L.w;
    }
#pragma unroll
    for (int e = 0; e < RPT; e++) rnk[e] = atomicAdd(&shA[lab[e]], 1);
    __syncthreads();

#pragma unroll
    for (int c = tid; c < CPAD; c += 256)
        g_parthist[myB * CPAD + c] = shA[c];

    // --- Grid barrier: all partial histograms visible ---
    grid_barrier();

    // --- Phase B: totals + own-prefix in one sweep (L2-hot, coalesced) ---
#pragma unroll 1
    for (int q = 0; q < 4; q++) {
        int c = tid + q * 256;
        int tot = 0, pre = 0;
#pragma unroll 8
        for (int b = 0; b < HB; b++) {
            int v = g_parthist[b * CPAD + c];
            tot += v;
            pre += (b < myB) ? v : 0;
        }
        shA[c] = tot;
        shP[c] = pre;
    }
    __syncthreads();

    // Block-wide exclusive scan over 1024 class totals (4 contiguous/thread).
    int t4 = tid * 4;
    int s0 = shA[t4], s1 = shA[t4 + 1], s2 = shA[t4 + 2], s3 = shA[t4 + 3];
    int mysum = s0 + s1 + s2 + s3;
    shS[tid] = mysum;
    __syncthreads();
#pragma unroll
    for (int off = 1; off < 256; off <<= 1) {
        int v = (tid >= off) ? shS[tid - off] : 0;
        __syncthreads();
        shS[tid] += v;
        __syncthreads();
    }
    int e0 = shS[tid] - mysum;          // exclusive offset of class t4
    int e1 = e0 + s0, e2 = e1 + s1, e3 = e2 + s2;

    if (myB == 0) {                     // publish for sum_ema
        if (t4 + 0 < NUM_CLASSES) { g_offsets[t4 + 0] = e0; g_counts[t4 + 0] = s0; }
        if (t4 + 1 < NUM_CLASSES) { g_offsets[t4 + 1] = e1; g_counts[t4 + 1] = s1; }
        if (t4 + 2 < NUM_CLASSES) { g_offsets[t4 + 2] = e2; g_counts[t4 + 2] = s2; }
        if (t4 + 3 < NUM_CLASSES) { g_offsets[t4 + 3] = e3; g_counts[t4 + 3] = s3; }
    }

    // This block's scatter base per class (overwrite shA — own-thread slots).
    shA[t4 + 0] = e0 + shP[t4 + 0];
    shA[t4 + 1] = e1 + shP[t4 + 1];
    shA[t4 + 2] = e2 + shP[t4 + 2];
    shA[t4 + 3] = e3 + shP[t4 + 3];
    __syncthreads();

    // --- Place: register-held rows straight to class-sorted order ---
    int rowbase = myB * ROWS_PER_HB;
#pragma unroll
    for (int k = 0; k < RPT / 4; k++) {
#pragma unroll
        for (int e = 0; e < 4; e++) {
            int idx = k * 4 + e;
            int row = rowbase + (tid + k * 256) * 4 + e;
            g_rowidx[shA[lab[idx]] + rnk[idx]] = row;
        }
    }
}

// ---------------------------------------------------------------------------
// K2: gather-sum + fused mean/EMA (unchanged — measured 71.8% DRAM).
// ---------------------------------------------------------------------------
#define F4ADD(a, b) { (a).x += (b).x; (a).y += (b).y; (a).z += (b).z; (a).w += (b).w; }

__global__ void __launch_bounds__(256, 4)
sum_ema_kernel(const float* __restrict__ features,
               const float* __restrict__ centers,
               float* __restrict__ out) {
    int tid = threadIdx.x;
    int r4 = tid >> 6;   // row slot 0..3
    int c4 = tid & 63;   // float4 column 0..63

    __shared__ float4 s[256];
    const float4* __restrict__ f4 = reinterpret_cast<const float4*>(features);

#pragma unroll 1
    for (int sub = 0; sub < 2; sub++) {
        int cls = blockIdx.x * 2 + sub;
        int n = g_counts[cls];
        const int* __restrict__ ridx = g_rowidx + g_offsets[cls];

        float4 a0 = make_float4(0.f, 0.f, 0.f, 0.f);
        float4 a1 = a0, a2 = a0, a3 = a0;

        int i = r4;
        for (; i + 12 < n; i += 16) {
            int i0 = ridx[i];
            int i1 = ridx[i + 4];
            int i2 = ridx[i + 8];
            int i3 = ridx[i + 12];
            float4 v0 = __ldcs(&f4[(size_t)i0 * 64 + c4]);
            float4 v1 = __ldcs(&f4[(size_t)i1 * 64 + c4]);
            float4 v2 = __ldcs(&f4[(size_t)i2 * 64 + c4]);
            float4 v3 = __ldcs(&f4[(size_t)i3 * 64 + c4]);
            F4ADD(a0, v0); F4ADD(a1, v1); F4ADD(a2, v2); F4ADD(a3, v3);
        }
        for (; i < n; i += 4) {
            int r = ridx[i];
            float4 v = __ldcs(&f4[(size_t)r * 64 + c4]);
            F4ADD(a0, v);
        }
        F4ADD(a0, a1); F4ADD(a2, a3); F4ADD(a0, a2);

        s[tid] = a0;
        __syncthreads();

        if (tid < 64) {
            float4 t0 = s[tid];
            float4 t1 = s[tid + 64];
            float4 t2 = s[tid + 128];
            float4 t3 = s[tid + 192];
            F4ADD(t0, t1); F4ADD(t2, t3); F4ADD(t0, t2);

            float4 c = reinterpret_cast<const float4*>(centers)[(size_t)cls * 64 + tid];
            float4 o;
            if (n > 0) {
                float scale = ALPHA / (float)n;   // ALPHA * mean
                o.x = (1.0f - ALPHA) * c.x + scale * t0.x;
                o.y = (1.0f - ALPHA) * c.y + scale * t0.y;
                o.z = (1.0f - ALPHA) * c.z + scale * t0.z;
                o.w = (1.0f - ALPHA) * c.w + scale * t0.w;
            } else {
                o = c;
            }
            reinterpret_cast<float4*>(out)[(size_t)cls * 64 + tid] = o;
        }
        __syncthreads();   // smem reuse safety for second class
    }
}

// ---------------------------------------------------------------------------
// Launch: features f32 [N,256], labels i32 [N], centers f32 [1000,256].
// ---------------------------------------------------------------------------
extern "C" void kernel_launch(void* const* d_in, const int* in_sizes, int n_in,
                              void* d_out, int out_size) {
    const float* features = (const float*)d_in[0];
    const int* labels     = (const int*)d_in[1];
    const float* centers  = (const float*)d_in[2];
    float* out            = (float*)d_out;

    index_kernel<<<HB, 256>>>(labels);
    sum_ema_kernel<<<NUM_CLASSES / 2, 256>>>(features, centers, out);
}